// round 15
// baseline (speedup 1.0000x reference)
#include <cuda_runtime.h>
#include <math.h>
#include <stdint.h>

// ---- scratch (device globals) ----
__device__ float d_W127[33*127];
__device__ float d_D64[33*64];
__device__ float d_tmpA[32*33*127];
__device__ float d_pos[32*33*33];
__device__ float d_tmpB[16*64*33];
__device__ float d_veH[16*64*64];
__device__ float d_qkv[8*256*4096];      // [n][o][h][w]
__device__ float d_p1s[1024*64], d_p1q[1024*64];
__device__ float d_m1[256], d_r1[256];
__device__ float d_qkvR[8*256*33*64];    // [n][o][i][w]
__device__ float d_sim[8*8*33*33*3*64];  // [n][g][i][j][part][w]  (interleaved)
__device__ float d_p2s[3*8*8*33], d_p2q[3*8*8*33];
__device__ float d_m2[192], d_r2[192];
__device__ float d_vb[8*8*16*64*64];     // [n][g][c][x][w]
__device__ float d_so[8*256*4096];       // [n][ch][y][w]
__device__ float d_p3[4096*16*4];        // bn3 partials per (block, c, comp)
__device__ float d_m3[256], d_r3[256];
__device__ float d_o[8*128*4096];        // [n][c][h][w]
__device__ float d_s4[1024*10];          // bn4 strip partials per (n,oc)
__device__ float d_m4[1024], d_r4[1024];
__device__ float d_h1[8*512*4096];

__device__ __forceinline__ void up_tap(int x, int &i0, int &i1, float &w0, float &w1) {
    float s = ((float)x + 0.5f) * (33.0f / 64.0f) - 0.5f;
    float fl = floorf(s);
    int i = (int)fl;
    float f = s - fl;
    if (i < 0)   { i = 0;  f = 0.f; }
    if (i >= 32) { i = 32; f = 0.f; }
    i0 = i; i1 = (i < 32) ? i + 1 : 32;
    w0 = 1.f - f; w1 = f;
}

__device__ __forceinline__ void reduce2(float &s, float &q) {
    __shared__ float sh1[256];
    __shared__ float sh2[256];
    int t = threadIdx.x;
    sh1[t] = s; sh2[t] = q;
    __syncthreads();
    for (int st = 128; st > 0; st >>= 1) {
        if (t < st) { sh1[t] += sh1[t+st]; sh2[t] += sh2[t+st]; }
        __syncthreads();
    }
    s = sh1[0]; q = sh2[0];
    __syncthreads();
}

__device__ __forceinline__ float tf32r(float x) {
    uint32_t o;
    asm("cvt.rna.tf32.f32 %0, %1;" : "=r"(o) : "f"(x));
    return __uint_as_float(o);
}

__global__ void k_weights() {
    int o = threadIdx.x;
    if (o >= 33) return;
    {
        const int IN = 127;
        float inv = (float)IN / 33.0f;
        float s = (o + 0.5f) * inv - 0.5f;
        float sum = 0.f;
        for (int i = 0; i < IN; i++) { float t = fmaxf(1.0f - fabsf(s-(float)i)/inv, 0.f); sum += t; }
        float is = 1.f / sum;
        for (int i = 0; i < IN; i++) { float t = fmaxf(1.0f - fabsf(s-(float)i)/inv, 0.f); d_W127[o*IN+i] = t*is; }
    }
    {
        const int IN = 64;
        float inv = (float)IN / 33.0f;
        float s = (o + 0.5f) * inv - 0.5f;
        float sum = 0.f;
        for (int i = 0; i < IN; i++) { float t = fmaxf(1.0f - fabsf(s-(float)i)/inv, 0.f); sum += t; }
        float is = 1.f / sum;
        for (int i = 0; i < IN; i++) { float t = fmaxf(1.0f - fabsf(s-(float)i)/inv, 0.f); d_D64[o*IN+i] = t*is; }
    }
}

__global__ void k_pos1(const float* __restrict__ br) {
    int idx = blockIdx.x * blockDim.x + threadIdx.x;
    if (idx >= 32*33*127) return;
    int x = idx % 127, i = (idx/127) % 33, cc = idx/(127*33);
    float acc = 0.f;
    for (int y = 0; y < 127; y++) acc += d_W127[i*127+y] * br[cc*16129 + y*127 + x];
    d_tmpA[cc*4191 + i*127 + x] = acc;
}

__global__ void k_pos2() {
    int idx = blockIdx.x * blockDim.x + threadIdx.x;
    if (idx >= 32*33*33) return;
    int j = idx % 33, i = (idx/33) % 33, cc = idx/1089;
    float acc = 0.f;
    for (int x = 0; x < 127; x++) acc += d_W127[j*127+x] * d_tmpA[cc*4191 + i*127 + x];
    d_pos[cc*1089 + i*33 + j] = acc;
}

__global__ void k_veh1() {
    int idx = blockIdx.x * blockDim.x + threadIdx.x;
    if (idx >= 16*64*33) return;
    int j = idx % 33, y = (idx/33) % 64, c = idx/2112;
    int i0, i1; float w0, w1; up_tap(y, i0, i1, w0, w1);
    d_tmpB[c*2112 + y*33 + j] = w0*d_pos[(16+c)*1089 + i0*33 + j] + w1*d_pos[(16+c)*1089 + i1*33 + j];
}

__global__ void k_veh2() {
    int idx = blockIdx.x * blockDim.x + threadIdx.x;
    if (idx >= 16*64*64) return;
    int x = idx % 64, y = (idx/64) % 64, c = idx/4096;
    int j0, j1; float w0, w1; up_tap(x, j0, j1, w0, w1);
    d_veH[(c*64+y)*64 + x] = w0*d_tmpB[c*2112 + y*33 + j0] + w1*d_tmpB[c*2112 + y*33 + j1];
}

// ---- tf32 tensor-core GEMM with register-prefetch double buffering ----
// C[n][m][p] = epi(sum_k A[m][k]*B[n][k][p]), P=4096.
// EPI 0: plain + bn1 partial stats (PS/PQ = partial outputs)
// EPI 1: B gathered on-the-fly from shifted d_o + instance-norm affine (PS=in_g, PQ=in_b); gelu epilogue
// EPI 2: +R residual epilogue
template<int EPI>
__global__ void __launch_bounds__(256) k_gemm_t(const float* __restrict__ A,
                                               const float* __restrict__ B,
                                               float* __restrict__ C,
                                               const float* __restrict__ R,
                                               float* __restrict__ PS,
                                               float* __restrict__ PQ,
                                               int M, int K) {
    const int LDA = 36, LDB = 136;
    __shared__ float As[64*36];
    __shared__ float Bs[32*136];
    __shared__ float pb[64][4][2];
    __shared__ float a4s[128], b4s[128];
    int n = blockIdx.z, m0 = blockIdx.y*64, p0 = blockIdx.x*128;
    const float* Ag = A + (size_t)m0*K;
    const float* Bg = B + (size_t)n*K*4096 + p0;
    const float* On = B + (size_t)n*K*4096;   // EPI1: d_o plane base for batch n
    int tid = threadIdx.x;
    int lane = tid & 31, ww = tid >> 5;
    int wm = (ww & 1)*32, wp = (ww >> 1)*32;
    int g = lane >> 2, tig = lane & 3;
    float c[2][4][4] = {};

    if (EPI == 1) {
        if (tid < 128) {
            int bidx = n*128 + tid;
            float a4 = PS[tid] * d_r4[bidx];
            a4s[tid] = a4;
            b4s[tid] = PQ[tid] - d_m4[bidx]*a4;
        }
        __syncthreads();
    }

    auto gather4 = [&](int ch, int p) -> float4 {
        int sc = ch, dh = 0, dw = 0;
        if      (ch < 10) {              dw = -2; }
        else if (ch < 20) { sc = ch-10;  dw =  2; }
        else if (ch < 30) { sc = ch-20;  dh = -2; }
        else if (ch < 40) { sc = ch-30;  dh =  2; }
        float a4 = a4s[ch], b4 = b4s[ch];
        int h = p >> 6, w = p & 63;
        float4 v;
        if (dw == 0) {
            int hh = h + dh;
            if (hh >= 0 && hh < 64) v = *(const float4*)&On[(size_t)sc*4096 + hh*64 + w];
            else v = make_float4(0.f, 0.f, 0.f, 0.f);
        } else {
            float e[4];
            #pragma unroll
            for (int q = 0; q < 4; q++) {
                int wwx = w + q + dw;
                e[q] = (wwx >= 0 && wwx < 64) ? On[(size_t)sc*4096 + h*64 + wwx] : 0.f;
            }
            v = make_float4(e[0], e[1], e[2], e[3]);
        }
        v.x = v.x*a4 + b4; v.y = v.y*a4 + b4; v.z = v.z*a4 + b4; v.w = v.w*a4 + b4;
        return v;
    };

    int am = (tid*2) >> 3, ak = ((tid*2) & 7)*4;
    int am2 = (tid*2+1) >> 3, ak2 = ((tid*2+1) & 7)*4;
    float4 ra[2], rb[4];
    int bk[4], bp[4];
    #pragma unroll
    for (int t = 0; t < 4; t++) { int i = tid + t*256; bk[t] = i >> 5; bp[t] = (i & 31)*4; }

    ra[0] = *(const float4*)&Ag[(size_t)am*K + ak];
    ra[1] = *(const float4*)&Ag[(size_t)am2*K + ak2];
    #pragma unroll
    for (int t = 0; t < 4; t++) {
        if (EPI == 1) rb[t] = gather4(bk[t], p0 + bp[t]);
        else          rb[t] = *(const float4*)&Bg[(size_t)bk[t]*4096 + bp[t]];
    }

    for (int k0 = 0; k0 < K; k0 += 32) {
        {
            float4 v = ra[0];
            v.x = tf32r(v.x); v.y = tf32r(v.y); v.z = tf32r(v.z); v.w = tf32r(v.w);
            *(float4*)&As[am*LDA + ak] = v;
            v = ra[1];
            v.x = tf32r(v.x); v.y = tf32r(v.y); v.z = tf32r(v.z); v.w = tf32r(v.w);
            *(float4*)&As[am2*LDA + ak2] = v;
            #pragma unroll
            for (int t = 0; t < 4; t++) {
                v = rb[t];
                v.x = tf32r(v.x); v.y = tf32r(v.y); v.z = tf32r(v.z); v.w = tf32r(v.w);
                *(float4*)&Bs[bk[t]*LDB + bp[t]] = v;
            }
        }
        __syncthreads();
        if (k0 + 32 < K) {
            ra[0] = *(const float4*)&Ag[(size_t)am*K + k0 + 32 + ak];
            ra[1] = *(const float4*)&Ag[(size_t)am2*K + k0 + 32 + ak2];
            #pragma unroll
            for (int t = 0; t < 4; t++) {
                if (EPI == 1) rb[t] = gather4(k0 + 32 + bk[t], p0 + bp[t]);
                else          rb[t] = *(const float4*)&Bg[(size_t)(k0 + 32 + bk[t])*4096 + bp[t]];
            }
        }
        #pragma unroll
        for (int kk = 0; kk < 32; kk += 8) {
            uint32_t a[2][4], b[4][2];
            #pragma unroll
            for (int mt = 0; mt < 2; mt++) {
                int mb = wm + mt*16;
                a[mt][0] = __float_as_uint(As[(mb+g  )*LDA + kk + tig]);
                a[mt][1] = __float_as_uint(As[(mb+g+8)*LDA + kk + tig]);
                a[mt][2] = __float_as_uint(As[(mb+g  )*LDA + kk + tig + 4]);
                a[mt][3] = __float_as_uint(As[(mb+g+8)*LDA + kk + tig + 4]);
            }
            #pragma unroll
            for (int pt = 0; pt < 4; pt++) {
                int pb2 = wp + pt*8 + g;
                b[pt][0] = __float_as_uint(Bs[(kk+tig  )*LDB + pb2]);
                b[pt][1] = __float_as_uint(Bs[(kk+tig+4)*LDB + pb2]);
            }
            #pragma unroll
            for (int mt = 0; mt < 2; mt++)
                #pragma unroll
                for (int pt = 0; pt < 4; pt++) {
                    asm volatile(
                        "mma.sync.aligned.m16n8k8.row.col.f32.tf32.tf32.f32 "
                        "{%0,%1,%2,%3}, {%4,%5,%6,%7}, {%8,%9}, {%0,%1,%2,%3};\n"
                        : "+f"(c[mt][pt][0]), "+f"(c[mt][pt][1]),
                          "+f"(c[mt][pt][2]), "+f"(c[mt][pt][3])
                        : "r"(a[mt][0]), "r"(a[mt][1]), "r"(a[mt][2]), "r"(a[mt][3]),
                          "r"(b[pt][0]), "r"(b[pt][1]));
                }
        }
        __syncthreads();
    }

    float* Cn = C + (size_t)n*M*4096;
    const float* Rn = R ? R + (size_t)n*M*4096 : nullptr;
    float prs[2][2] = {}, prq[2][2] = {};
    #pragma unroll
    for (int mt = 0; mt < 2; mt++) {
        #pragma unroll
        for (int pt = 0; pt < 4; pt++) {
            int pc = p0 + wp + pt*8 + tig*2;
            #pragma unroll
            for (int e = 0; e < 4; e++) {
                int m = m0 + wm + mt*16 + g + ((e >> 1) ? 8 : 0);
                int p = pc + (e & 1);
                float v = c[mt][pt][e];
                if (EPI == 1) v = 0.5f*v*(1.0f + erff(v*0.70710678118654752f));
                if (EPI == 2) v += Rn[(size_t)m*4096 + p];
                Cn[(size_t)m*4096 + p] = v;
                if (EPI == 0) { prs[mt][e>>1] += v; prq[mt][e>>1] += v*v; }
            }
        }
    }
    if (EPI == 0) {
        #pragma unroll
        for (int mt = 0; mt < 2; mt++)
            #pragma unroll
            for (int h = 0; h < 2; h++) {
                float s = prs[mt][h], q = prq[mt][h];
                s += __shfl_down_sync(0xffffffffu, s, 1);
                s += __shfl_down_sync(0xffffffffu, s, 2);
                q += __shfl_down_sync(0xffffffffu, q, 1);
                q += __shfl_down_sync(0xffffffffu, q, 2);
                if (tig == 0) {
                    int ml = wm + mt*16 + h*8 + g;
                    pb[ml][ww>>1][0] = s;
                    pb[ml][ww>>1][1] = q;
                }
            }
        __syncthreads();
        if (tid < 64) {
            float s = pb[tid][0][0] + pb[tid][1][0] + pb[tid][2][0] + pb[tid][3][0];
            float q = pb[tid][0][1] + pb[tid][1][1] + pb[tid][2][1] + pb[tid][3][1];
            int idx = ((n*4 + blockIdx.y)*32 + blockIdx.x)*64 + tid;
            PS[idx] = s; PQ[idx] = q;
        }
    }
}

// bn1 stats from gemm0 partials
__global__ void k_bn1r() {
    __shared__ float s1[64], s2[64];
    int o = blockIdx.x;
    int my = o >> 6, row = o & 63;
    int tid = threadIdx.x;
    float s = 0.f, q = 0.f;
    for (int t = tid; t < 256; t += 64) {
        int n = t >> 5, px = t & 31;
        int idx = ((n*4 + my)*32 + px)*64 + row;
        s += d_p1s[idx]; q += d_p1q[idx];
    }
    s1[tid] = s; s2[tid] = q;
    __syncthreads();
    for (int st = 32; st > 0; st >>= 1) {
        if (tid < st) { s1[tid] += s1[tid+st]; s2[tid] += s2[tid+st]; }
        __syncthreads();
    }
    if (tid == 0) {
        float m = s1[0]*(1.f/32768.f);
        d_m1[o] = m;
        d_r1[o] = rsqrtf(s2[0]*(1.f/32768.f) - m*m + 1e-5f);
    }
}

__global__ void __launch_bounds__(256) k_resizeH(const float* __restrict__ gg,
                                                 const float* __restrict__ bb) {
    __shared__ float pl[4096];
    int o = blockIdx.x, n = blockIdx.y, tid = threadIdx.x;
    const float* src = d_qkv + (size_t)(n*256+o)*4096;
    for (int t = tid; t < 4096; t += 256) pl[t] = src[t];
    __syncthreads();
    float a = gg[o]*d_r1[o];
    float b2 = bb[o] - d_m1[o]*a;
    for (int t = tid; t < 33*64; t += 256) {
        int w = t & 63, i = t >> 6;
        float acc = 0.f;
        #pragma unroll 16
        for (int h = 0; h < 64; h++) acc += d_D64[i*64+h] * pl[h*64 + w];
        d_qkvR[((size_t)(n*256+o)*33 + i)*64 + w] = acc*a + b2;
    }
}

// sim (interleaved [part][w]) + BN2 partial stats
__global__ void __launch_bounds__(64) k_sim() {
    __shared__ float sh[6*64];
    int i = blockIdx.x, g = blockIdx.y, n = blockIdx.z, w = threadIdx.x;
    float qa[8];
    #pragma unroll
    for (int c = 0; c < 8; c++)
        qa[c] = d_qkvR[((size_t)(n*256 + g*32 + c)*33 + i)*64 + w];
    size_t rowbase = (((size_t)(n*8+g)*33 + i)*33)*192;
    float p[6] = {0.f,0.f,0.f,0.f,0.f,0.f};
    for (int j = 0; j < 33; j++) {
        float qk = 0.f, kr = 0.f, qr = 0.f;
        #pragma unroll
        for (int c = 0; c < 8; c++) {
            float kv = d_qkvR[((size_t)(n*256 + g*32 + 8 + c)*33 + j)*64 + w];
            qk += qa[c]*kv;
            kr += kv * d_pos[(8+c)*1089 + j*33 + i];
            qr += qa[c] * d_pos[c*1089 + i*33 + j];
        }
        d_sim[rowbase + j*192 + w]       = qk;
        d_sim[rowbase + j*192 + 64 + w]  = qr;
        d_sim[rowbase + j*192 + 128 + w] = kr;
        p[0] += qk; p[1] += qk*qk;
        p[2] += qr; p[3] += qr*qr;
        p[4] += kr; p[5] += kr*kr;
    }
    #pragma unroll
    for (int r = 0; r < 6; r++) sh[r*64 + w] = p[r];
    __syncthreads();
    for (int st = 32; st > 0; st >>= 1) {
        if (w < st) {
            #pragma unroll
            for (int r = 0; r < 6; r++) sh[r*64 + w] += sh[r*64 + w + st];
        }
        __syncthreads();
    }
    if (w == 0) {
        int base = (n*8+g)*33 + i;
        #pragma unroll
        for (int t = 0; t < 3; t++) {
            d_p2s[t*2112 + base] = sh[(2*t)*64];
            d_p2q[t*2112 + base] = sh[(2*t+1)*64];
        }
    }
}

__global__ void k_bn2() {
    __shared__ float ss[33], qq[33];
    int b = blockIdx.x;            // n*24 + ch
    int n = b / 24, ch = b % 24;
    int t = ch >> 3, g = ch & 7;
    int i = threadIdx.x;
    if (i < 33) {
        int idx = t*2112 + (n*8+g)*33 + i;
        ss[i] = d_p2s[idx];
        qq[i] = d_p2q[idx];
    }
    __syncthreads();
    if (i == 0) {
        float s = 0.f, q = 0.f;
        for (int k = 0; k < 33; k++) { s += ss[k]; q += qq[k]; }
        float m = s/69696.f;
        d_m2[b] = m;
        d_r2[b] = rsqrtf(q/69696.f - m*m + 1e-5f);
    }
}

// vb: [n][g][c][x][w]
__global__ void k_vb() {
    int idx = blockIdx.x * blockDim.x + threadIdx.x;
    if (idx >= 8*8*16*64*64) return;
    int w = idx & 63, x = (idx>>6) & 63, c = (idx>>12) & 15;
    int g = (idx>>16) & 7, n = idx>>19;
    int j0, j1; float w0, w1; up_tap(x, j0, j1, w0, w1);
    size_t b = (size_t)(n*256 + g*32 + 16 + c)*2112 + w;
    d_vb[idx] = w0*d_qkvR[b + j0*64] + w1*d_qkvR[b + j1*64];
}

// fused: BN2-apply + 3-sum + y-interp + x-interp + softmax + attention + BN3 partials
// 2 y per block (128 threads): vb lines loaded by the y0 half are L1 hits for the y1 half.
__global__ void __launch_bounds__(128) k_softsv(const float* __restrict__ gg,
                                                const float* __restrict__ bb) {
    __shared__ float srj[2*33*64];
    __shared__ float ps[16][4][4];
    int yp = blockIdx.x, g = blockIdx.y, n = blockIdx.z;
    int tid = threadIdx.x, w = tid & 63, yl = tid >> 6;
    int y = yp*2 + yl;
    int warp = tid >> 5, lane = tid & 31;
    int i0, i1; float v0, v1; up_tap(y, i0, i1, v0, v1);

    float a0, a1t, a2t, C = 0.f;
    {
        int sc0 = n*24 + g,      ch0 = g;
        int sc1 = n*24 + 8 + g,  ch1 = 8 + g;
        int sc2 = n*24 + 16 + g, ch2 = 16 + g;
        a0  = gg[ch0]*d_r2[sc0]; C += bb[ch0] - d_m2[sc0]*a0;
        a1t = gg[ch1]*d_r2[sc1]; C += bb[ch1] - d_m2[sc1]*a1t;
        a2t = gg[ch2]*d_r2[sc2]; C += bb[ch2] - d_m2[sc2]*a2t;
    }

    const float* r0 = d_sim + (((size_t)(n*8+g)*33 + i0)*33)*192;
    const float* r1 = d_sim + (((size_t)(n*8+g)*33 + i1)*33)*192;
    float* sr = srj + yl*2112;
    #pragma unroll 3
    for (int j = 0; j < 33; j++) {
        int off = j*192 + w;
        float acc = C;
        acc += a0 *(v0*r0[off]       + v1*r1[off]);
        acc += a1t*(v0*r0[off + 64]  + v1*r1[off + 64]);
        acc += a2t*(v0*r0[off + 128] + v1*r1[off + 128]);
        sr[j*64 + w] = acc;
    }
    // each thread reads only entries it wrote (its own yl half, its own w) — no sync
    float row[64];
    #pragma unroll
    for (int x = 0; x < 64; x++) {
        int j0, j1; float u0, u1; up_tap(x, j0, j1, u0, u1);
        row[x] = u0*sr[j0*64 + w] + u1*sr[j1*64 + w];
    }
    float mx = row[0];
    #pragma unroll
    for (int x = 1; x < 64; x++) mx = fmaxf(mx, row[x]);
    float s = 0.f;
    #pragma unroll
    for (int x = 0; x < 64; x++) { row[x] = expf(row[x]-mx); s += row[x]; }
    float inv = 1.f/s;
    #pragma unroll
    for (int x = 0; x < 64; x++) row[x] *= inv;

    const float* vbg = d_vb + ((size_t)(n*8+g)*16)*4096 + w;
    #pragma unroll 2
    for (int c = 0; c < 16; c++) {
        const float* vbp = vbg + (size_t)c*4096;
        const float* vep = d_veH + (c*64 + y)*64;
        float asv = 0.f, asve = 0.f;
        #pragma unroll 8
        for (int x = 0; x < 64; x++) {
            float sx = row[x];
            asv  += sx * vbp[x*64];
            asve += sx * vep[x];
        }
        int ch = g*32 + c*2;
        size_t ob = ((size_t)(n*256 + ch)*64 + y)*64 + w;
        d_so[ob] = asv;
        d_so[ob + 4096] = asve;
        float t0 = asv, t1 = asv*asv, t2 = asve, t3 = asve*asve;
        #pragma unroll
        for (int st = 16; st > 0; st >>= 1) {
            t0 += __shfl_down_sync(0xffffffffu, t0, st);
            t1 += __shfl_down_sync(0xffffffffu, t1, st);
            t2 += __shfl_down_sync(0xffffffffu, t2, st);
            t3 += __shfl_down_sync(0xffffffffu, t3, st);
        }
        if (lane == 0) { ps[c][warp][0]=t0; ps[c][warp][1]=t1; ps[c][warp][2]=t2; ps[c][warp][3]=t3; }
    }
    __syncthreads();
    // combine warps {0,1} for y0, {2,3} for y1
    if (tid < 16) {
        int blk = ((n*8+g)*64 + yp*2);
        #pragma unroll
        for (int comp = 0; comp < 4; comp++)
            d_p3[((size_t)blk*16 + tid)*4 + comp] = ps[tid][0][comp] + ps[tid][1][comp];
    } else if (tid >= 64 && tid < 80) {
        int c = tid - 64;
        int blk = ((n*8+g)*64 + yp*2 + 1);
        #pragma unroll
        for (int comp = 0; comp < 4; comp++)
            d_p3[((size_t)blk*16 + c)*4 + comp] = ps[c][2][comp] + ps[c][3][comp];
    }
}

// bn3 from partials
__global__ void k_bn3r() {
    __shared__ float sh1[128], sh2[128];
    int ch = blockIdx.x;
    int g = ch >> 5, c = (ch & 31) >> 1, e = ch & 1;
    int tid = threadIdx.x;
    float s = 0.f, q = 0.f;
    for (int t = tid; t < 512; t += 128) {
        int n = t >> 6, y = t & 63;
        size_t idx = ((size_t)((n*8+g)*64 + y)*16 + c)*4 + e*2;
        s += d_p3[idx]; q += d_p3[idx+1];
    }
    sh1[tid] = s; sh2[tid] = q;
    __syncthreads();
    for (int st = 64; st > 0; st >>= 1) {
        if (tid < st) { sh1[tid] += sh1[tid+st]; sh2[tid] += sh2[tid+st]; }
        __syncthreads();
    }
    if (tid == 0) {
        float m = sh1[0]*(1.f/32768.f);
        d_m3[ch] = m;
        d_r3[ch] = rsqrtf(sh2[0]*(1.f/32768.f) - m*m + 1e-5f);
    }
}

// o = BN3(so)[2oc]+BN3(so)[2oc+1], plus bn4 strip partials; one block per (n,oc)
__global__ void __launch_bounds__(256) k_o(const float* __restrict__ gg,
                                           const float* __restrict__ bb) {
    int oc = blockIdx.x & 127, n = blockIdx.x >> 7;
    int tid = threadIdx.x;
    float a0, b0, a1, b1;
    {
        int c0 = 2*oc, c1 = 2*oc + 1;
        a0 = gg[c0]*d_r3[c0]; b0 = bb[c0] - d_m3[c0]*a0;
        a1 = gg[c1]*d_r3[c1]; b1 = bb[c1] - d_m3[c1]*a1;
    }
    const float* p0 = d_so + (size_t)(n*256 + 2*oc)*4096;
    const float* p1 = p0 + 4096;
    float* po = d_o + (size_t)(n*128 + oc)*4096;
    float acc10[10];
    #pragma unroll
    for (int r = 0; r < 10; r++) acc10[r] = 0.f;
    for (int t = tid; t < 4096; t += 256) {
        float v = p0[t]*a0 + b0 + p1[t]*a1 + b1;
        po[t] = v;
        float v2 = v*v;
        acc10[0] += v; acc10[1] += v2;
        int w = t & 63, h = t >> 6;
        if (w < 2)  { acc10[2] += v; acc10[3] += v2; }
        if (w >= 62){ acc10[4] += v; acc10[5] += v2; }
        if (h < 2)  { acc10[6] += v; acc10[7] += v2; }
        if (h >= 62){ acc10[8] += v; acc10[9] += v2; }
    }
    #pragma unroll
    for (int r = 0; r < 10; r += 2) reduce2(acc10[r], acc10[r+1]);
    if (tid == 0) {
        #pragma unroll
        for (int r = 0; r < 10; r++) d_s4[(n*128 + oc)*10 + r] = acc10[r];
    }
}

// bn4 stats from strip partials
__global__ void k_bn4r() {
    int idx = blockIdx.x*256 + threadIdx.x;
    if (idx >= 1024) return;
    int n = idx >> 7, ch = idx & 127;
    int sc = ch, sub = -1;
    if      (ch < 10) { sc = ch;      sub = 4; }
    else if (ch < 20) { sc = ch - 10; sub = 2; }
    else if (ch < 30) { sc = ch - 20; sub = 8; }
    else if (ch < 40) { sc = ch - 30; sub = 6; }
    const float* s4 = d_s4 + (n*128 + sc)*10;
    float S = s4[0], Q = s4[1];
    if (sub >= 0) { S -= s4[sub]; Q -= s4[sub+1]; }
    float m = S*(1.f/4096.f);
    d_m4[idx] = m;
    d_r4[idx] = rsqrtf(Q*(1.f/4096.f) - m*m + 1e-5f);
}

extern "C" void kernel_launch(void* const* d_in, const int* in_sizes, int n_in,
                              void* d_out, int out_size) {
    const float* x        = (const float*)d_in[0];
    const float* qkv_w    = (const float*)d_in[1];
    const float* bn_qkv_g = (const float*)d_in[2];
    const float* bn_qkv_b = (const float*)d_in[3];
    const float* base_rel = (const float*)d_in[4];
    const float* bn_sim_g = (const float*)d_in[5];
    const float* bn_sim_b = (const float*)d_in[6];
    const float* bn_out_g = (const float*)d_in[7];
    const float* bn_out_b = (const float*)d_in[8];
    const float* in_g     = (const float*)d_in[9];
    const float* in_b     = (const float*)d_in[10];
    const float* mlp_w1   = (const float*)d_in[11];
    const float* mlp_w2   = (const float*)d_in[12];
    float* out = (float*)d_out;

    float *pqkv, *po, *ph1, *pp1s, *pp1q;
    cudaGetSymbolAddress((void**)&pqkv, d_qkv);
    cudaGetSymbolAddress((void**)&po,   d_o);
    cudaGetSymbolAddress((void**)&ph1,  d_h1);
    cudaGetSymbolAddress((void**)&pp1s, d_p1s);
    cudaGetSymbolAddress((void**)&pp1q, d_p1q);

    k_weights<<<1, 64>>>();
    k_pos1<<<(32*33*127 + 255)/256, 256>>>(base_rel);
    k_pos2<<<(32*33*33 + 255)/256, 256>>>();
    k_gemm_t<0><<<dim3(32, 4, 8), 256>>>(qkv_w, x, pqkv, nullptr, pp1s, pp1q, 256, 128);
    k_bn1r<<<256, 64>>>();
    k_resizeH<<<dim3(256, 8), 256>>>(bn_qkv_g, bn_qkv_b);
    k_sim<<<dim3(33, 8, 8), 64>>>();
    k_bn2<<<192, 64>>>();
    k_veh1<<<(16*64*33 + 255)/256, 256>>>();
    k_veh2<<<(16*64*64 + 255)/256, 256>>>();
    k_vb<<<(8*8*16*64*64 + 255)/256, 256>>>();
    k_softsv<<<dim3(32, 8, 8), 128>>>(bn_sim_g, bn_sim_b);
    k_bn3r<<<256, 128>>>();
    k_o<<<1024, 256>>>(bn_out_g, bn_out_b);
    k_bn4r<<<4, 256>>>();
    k_gemm_t<1><<<dim3(32, 8, 8), 256>>>(mlp_w1, po, ph1, nullptr,
                                         (float*)in_g, (float*)in_b, 512, 128);
    k_gemm_t<2><<<dim3(32, 2, 8), 256>>>(mlp_w2, ph1, out, po, nullptr, nullptr, 128, 512);
}

// round 16
// speedup vs baseline: 1.0235x; 1.0235x over previous
#include <cuda_runtime.h>
#include <math.h>
#include <stdint.h>

// ---- scratch (device globals) ----
__device__ float d_W127[33*127];
__device__ float d_D64[33*64];
__device__ float d_tmpA[32*33*127];
__device__ float d_pos[32*33*33];
__device__ float d_tmpB[16*64*33];
__device__ float d_veH[16*64*64];
__device__ float d_qkv[8*256*4096];      // [n][o][h][w]
__device__ float d_p1s[1024*64], d_p1q[1024*64];
__device__ float d_m1[256], d_r1[256];
__device__ float d_qkvR[8*256*33*64];    // [n][o][i][w]
__device__ float d_sim[8*8*33*33*3*64];  // [n][g][i][j][part][w]  (interleaved)
__device__ float d_p2s[3*8*8*33], d_p2q[3*8*8*33];
__device__ float d_m2[192], d_r2[192];
__device__ float d_vb[8*8*16*64*64];     // [n][g][c][x][w]
__device__ float d_so[8*256*4096];       // [n][ch][y][w]
__device__ float d_p3[4096*16*4];        // bn3 partials per (block, c, comp)
__device__ float d_m3[256], d_r3[256];
__device__ float d_o[8*128*4096];        // [n][c][h][w]
__device__ float d_s4[1024*10];          // bn4 strip partials per (n,oc)
__device__ float d_m4[1024], d_r4[1024];
__device__ float d_h1[8*512*4096];

__device__ __forceinline__ void up_tap(int x, int &i0, int &i1, float &w0, float &w1) {
    float s = ((float)x + 0.5f) * (33.0f / 64.0f) - 0.5f;
    float fl = floorf(s);
    int i = (int)fl;
    float f = s - fl;
    if (i < 0)   { i = 0;  f = 0.f; }
    if (i >= 32) { i = 32; f = 0.f; }
    i0 = i; i1 = (i < 32) ? i + 1 : 32;
    w0 = 1.f - f; w1 = f;
}

__device__ __forceinline__ void reduce2(float &s, float &q) {
    __shared__ float sh1[256];
    __shared__ float sh2[256];
    int t = threadIdx.x;
    sh1[t] = s; sh2[t] = q;
    __syncthreads();
    for (int st = 128; st > 0; st >>= 1) {
        if (t < st) { sh1[t] += sh1[t+st]; sh2[t] += sh2[t+st]; }
        __syncthreads();
    }
    s = sh1[0]; q = sh2[0];
    __syncthreads();
}

__device__ __forceinline__ float tf32r(float x) {
    uint32_t o;
    asm("cvt.rna.tf32.f32 %0, %1;" : "=r"(o) : "f"(x));
    return __uint_as_float(o);
}

__global__ void k_weights() {
    int o = threadIdx.x;
    if (o >= 33) return;
    {
        const int IN = 127;
        float inv = (float)IN / 33.0f;
        float s = (o + 0.5f) * inv - 0.5f;
        float sum = 0.f;
        for (int i = 0; i < IN; i++) { float t = fmaxf(1.0f - fabsf(s-(float)i)/inv, 0.f); sum += t; }
        float is = 1.f / sum;
        for (int i = 0; i < IN; i++) { float t = fmaxf(1.0f - fabsf(s-(float)i)/inv, 0.f); d_W127[o*IN+i] = t*is; }
    }
    {
        const int IN = 64;
        float inv = (float)IN / 33.0f;
        float s = (o + 0.5f) * inv - 0.5f;
        float sum = 0.f;
        for (int i = 0; i < IN; i++) { float t = fmaxf(1.0f - fabsf(s-(float)i)/inv, 0.f); sum += t; }
        float is = 1.f / sum;
        for (int i = 0; i < IN; i++) { float t = fmaxf(1.0f - fabsf(s-(float)i)/inv, 0.f); d_D64[o*IN+i] = t*is; }
    }
}

__global__ void k_pos1(const float* __restrict__ br) {
    int idx = blockIdx.x * blockDim.x + threadIdx.x;
    if (idx >= 32*33*127) return;
    int x = idx % 127, i = (idx/127) % 33, cc = idx/(127*33);
    float acc = 0.f;
    for (int y = 0; y < 127; y++) acc += d_W127[i*127+y] * br[cc*16129 + y*127 + x];
    d_tmpA[cc*4191 + i*127 + x] = acc;
}

__global__ void k_pos2() {
    int idx = blockIdx.x * blockDim.x + threadIdx.x;
    if (idx >= 32*33*33) return;
    int j = idx % 33, i = (idx/33) % 33, cc = idx/1089;
    float acc = 0.f;
    for (int x = 0; x < 127; x++) acc += d_W127[j*127+x] * d_tmpA[cc*4191 + i*127 + x];
    d_pos[cc*1089 + i*33 + j] = acc;
}

__global__ void k_veh1() {
    int idx = blockIdx.x * blockDim.x + threadIdx.x;
    if (idx >= 16*64*33) return;
    int j = idx % 33, y = (idx/33) % 64, c = idx/2112;
    int i0, i1; float w0, w1; up_tap(y, i0, i1, w0, w1);
    d_tmpB[c*2112 + y*33 + j] = w0*d_pos[(16+c)*1089 + i0*33 + j] + w1*d_pos[(16+c)*1089 + i1*33 + j];
}

__global__ void k_veh2() {
    int idx = blockIdx.x * blockDim.x + threadIdx.x;
    if (idx >= 16*64*64) return;
    int x = idx % 64, y = (idx/64) % 64, c = idx/4096;
    int j0, j1; float w0, w1; up_tap(x, j0, j1, w0, w1);
    d_veH[(c*64+y)*64 + x] = w0*d_tmpB[c*2112 + y*33 + j0] + w1*d_tmpB[c*2112 + y*33 + j1];
}

// ---- tf32 tensor-core GEMM with register-prefetch double buffering ----
// C[n][m][p] = epi(sum_k A[m][k]*B[n][k][p]), P=4096.
// EPI 0: plain + bn1 partial stats (PS/PQ = partial outputs)
// EPI 1: B gathered on-the-fly from shifted d_o + instance-norm affine (PS=in_g, PQ=in_b); gelu epilogue
// EPI 2: +R residual epilogue
template<int EPI>
__global__ void __launch_bounds__(256) k_gemm_t(const float* __restrict__ A,
                                               const float* __restrict__ B,
                                               float* __restrict__ C,
                                               const float* __restrict__ R,
                                               float* __restrict__ PS,
                                               float* __restrict__ PQ,
                                               int M, int K) {
    const int LDA = 36, LDB = 136;
    __shared__ float As[64*36];
    __shared__ float Bs[32*136];
    __shared__ float pb[64][4][2];
    __shared__ float a4s[128], b4s[128];
    int n = blockIdx.z, m0 = blockIdx.y*64, p0 = blockIdx.x*128;
    const float* Ag = A + (size_t)m0*K;
    const float* Bg = B + (size_t)n*K*4096 + p0;
    const float* On = B + (size_t)n*K*4096;   // EPI1: d_o plane base for batch n
    int tid = threadIdx.x;
    int lane = tid & 31, ww = tid >> 5;
    int wm = (ww & 1)*32, wp = (ww >> 1)*32;
    int g = lane >> 2, tig = lane & 3;
    float c[2][4][4] = {};

    if (EPI == 1) {
        if (tid < 128) {
            int bidx = n*128 + tid;
            float a4 = PS[tid] * d_r4[bidx];
            a4s[tid] = a4;
            b4s[tid] = PQ[tid] - d_m4[bidx]*a4;
        }
        __syncthreads();
    }

    auto gather4 = [&](int ch, int p) -> float4 {
        int sc = ch, dh = 0, dw = 0;
        if      (ch < 10) {              dw = -2; }
        else if (ch < 20) { sc = ch-10;  dw =  2; }
        else if (ch < 30) { sc = ch-20;  dh = -2; }
        else if (ch < 40) { sc = ch-30;  dh =  2; }
        float a4 = a4s[ch], b4 = b4s[ch];
        int h = p >> 6, w = p & 63;
        float4 v;
        if (dw == 0) {
            int hh = h + dh;
            if (hh >= 0 && hh < 64) v = *(const float4*)&On[(size_t)sc*4096 + hh*64 + w];
            else v = make_float4(0.f, 0.f, 0.f, 0.f);
        } else {
            float e[4];
            #pragma unroll
            for (int q = 0; q < 4; q++) {
                int wwx = w + q + dw;
                e[q] = (wwx >= 0 && wwx < 64) ? On[(size_t)sc*4096 + h*64 + wwx] : 0.f;
            }
            v = make_float4(e[0], e[1], e[2], e[3]);
        }
        v.x = v.x*a4 + b4; v.y = v.y*a4 + b4; v.z = v.z*a4 + b4; v.w = v.w*a4 + b4;
        return v;
    };

    int am = (tid*2) >> 3, ak = ((tid*2) & 7)*4;
    int am2 = (tid*2+1) >> 3, ak2 = ((tid*2+1) & 7)*4;
    float4 ra[2], rb[4];
    int bk[4], bp[4];
    #pragma unroll
    for (int t = 0; t < 4; t++) { int i = tid + t*256; bk[t] = i >> 5; bp[t] = (i & 31)*4; }

    ra[0] = *(const float4*)&Ag[(size_t)am*K + ak];
    ra[1] = *(const float4*)&Ag[(size_t)am2*K + ak2];
    #pragma unroll
    for (int t = 0; t < 4; t++) {
        if (EPI == 1) rb[t] = gather4(bk[t], p0 + bp[t]);
        else          rb[t] = *(const float4*)&Bg[(size_t)bk[t]*4096 + bp[t]];
    }

    for (int k0 = 0; k0 < K; k0 += 32) {
        {
            float4 v = ra[0];
            v.x = tf32r(v.x); v.y = tf32r(v.y); v.z = tf32r(v.z); v.w = tf32r(v.w);
            *(float4*)&As[am*LDA + ak] = v;
            v = ra[1];
            v.x = tf32r(v.x); v.y = tf32r(v.y); v.z = tf32r(v.z); v.w = tf32r(v.w);
            *(float4*)&As[am2*LDA + ak2] = v;
            #pragma unroll
            for (int t = 0; t < 4; t++) {
                v = rb[t];
                v.x = tf32r(v.x); v.y = tf32r(v.y); v.z = tf32r(v.z); v.w = tf32r(v.w);
                *(float4*)&Bs[bk[t]*LDB + bp[t]] = v;
            }
        }
        __syncthreads();
        if (k0 + 32 < K) {
            ra[0] = *(const float4*)&Ag[(size_t)am*K + k0 + 32 + ak];
            ra[1] = *(const float4*)&Ag[(size_t)am2*K + k0 + 32 + ak2];
            #pragma unroll
            for (int t = 0; t < 4; t++) {
                if (EPI == 1) rb[t] = gather4(k0 + 32 + bk[t], p0 + bp[t]);
                else          rb[t] = *(const float4*)&Bg[(size_t)(k0 + 32 + bk[t])*4096 + bp[t]];
            }
        }
        #pragma unroll
        for (int kk = 0; kk < 32; kk += 8) {
            uint32_t a[2][4], b[4][2];
            #pragma unroll
            for (int mt = 0; mt < 2; mt++) {
                int mb = wm + mt*16;
                a[mt][0] = __float_as_uint(As[(mb+g  )*LDA + kk + tig]);
                a[mt][1] = __float_as_uint(As[(mb+g+8)*LDA + kk + tig]);
                a[mt][2] = __float_as_uint(As[(mb+g  )*LDA + kk + tig + 4]);
                a[mt][3] = __float_as_uint(As[(mb+g+8)*LDA + kk + tig + 4]);
            }
            #pragma unroll
            for (int pt = 0; pt < 4; pt++) {
                int pb2 = wp + pt*8 + g;
                b[pt][0] = __float_as_uint(Bs[(kk+tig  )*LDB + pb2]);
                b[pt][1] = __float_as_uint(Bs[(kk+tig+4)*LDB + pb2]);
            }
            #pragma unroll
            for (int mt = 0; mt < 2; mt++)
                #pragma unroll
                for (int pt = 0; pt < 4; pt++) {
                    asm volatile(
                        "mma.sync.aligned.m16n8k8.row.col.f32.tf32.tf32.f32 "
                        "{%0,%1,%2,%3}, {%4,%5,%6,%7}, {%8,%9}, {%0,%1,%2,%3};\n"
                        : "+f"(c[mt][pt][0]), "+f"(c[mt][pt][1]),
                          "+f"(c[mt][pt][2]), "+f"(c[mt][pt][3])
                        : "r"(a[mt][0]), "r"(a[mt][1]), "r"(a[mt][2]), "r"(a[mt][3]),
                          "r"(b[pt][0]), "r"(b[pt][1]));
                }
        }
        __syncthreads();
    }

    float* Cn = C + (size_t)n*M*4096;
    const float* Rn = R ? R + (size_t)n*M*4096 : nullptr;
    float prs[2][2] = {}, prq[2][2] = {};
    #pragma unroll
    for (int mt = 0; mt < 2; mt++) {
        #pragma unroll
        for (int pt = 0; pt < 4; pt++) {
            int pc = p0 + wp + pt*8 + tig*2;
            #pragma unroll
            for (int e = 0; e < 4; e++) {
                int m = m0 + wm + mt*16 + g + ((e >> 1) ? 8 : 0);
                int p = pc + (e & 1);
                float v = c[mt][pt][e];
                if (EPI == 1) v = 0.5f*v*(1.0f + erff(v*0.70710678118654752f));
                if (EPI == 2) v += Rn[(size_t)m*4096 + p];
                Cn[(size_t)m*4096 + p] = v;
                if (EPI == 0) { prs[mt][e>>1] += v; prq[mt][e>>1] += v*v; }
            }
        }
    }
    if (EPI == 0) {
        #pragma unroll
        for (int mt = 0; mt < 2; mt++)
            #pragma unroll
            for (int h = 0; h < 2; h++) {
                float s = prs[mt][h], q = prq[mt][h];
                s += __shfl_down_sync(0xffffffffu, s, 1);
                s += __shfl_down_sync(0xffffffffu, s, 2);
                q += __shfl_down_sync(0xffffffffu, q, 1);
                q += __shfl_down_sync(0xffffffffu, q, 2);
                if (tig == 0) {
                    int ml = wm + mt*16 + h*8 + g;
                    pb[ml][ww>>1][0] = s;
                    pb[ml][ww>>1][1] = q;
                }
            }
        __syncthreads();
        if (tid < 64) {
            float s = pb[tid][0][0] + pb[tid][1][0] + pb[tid][2][0] + pb[tid][3][0];
            float q = pb[tid][0][1] + pb[tid][1][1] + pb[tid][2][1] + pb[tid][3][1];
            int idx = ((n*4 + blockIdx.y)*32 + blockIdx.x)*64 + tid;
            PS[idx] = s; PQ[idx] = q;
        }
    }
}

// bn1 stats from gemm0 partials
__global__ void k_bn1r() {
    __shared__ float s1[64], s2[64];
    int o = blockIdx.x;
    int my = o >> 6, row = o & 63;
    int tid = threadIdx.x;
    float s = 0.f, q = 0.f;
    for (int t = tid; t < 256; t += 64) {
        int n = t >> 5, px = t & 31;
        int idx = ((n*4 + my)*32 + px)*64 + row;
        s += d_p1s[idx]; q += d_p1q[idx];
    }
    s1[tid] = s; s2[tid] = q;
    __syncthreads();
    for (int st = 32; st > 0; st >>= 1) {
        if (tid < st) { s1[tid] += s1[tid+st]; s2[tid] += s2[tid+st]; }
        __syncthreads();
    }
    if (tid == 0) {
        float m = s1[0]*(1.f/32768.f);
        d_m1[o] = m;
        d_r1[o] = rsqrtf(s2[0]*(1.f/32768.f) - m*m + 1e-5f);
    }
}

__global__ void __launch_bounds__(256) k_resizeH(const float* __restrict__ gg,
                                                 const float* __restrict__ bb) {
    __shared__ float pl[4096];
    int o = blockIdx.x, n = blockIdx.y, tid = threadIdx.x;
    const float* src = d_qkv + (size_t)(n*256+o)*4096;
    for (int t = tid; t < 4096; t += 256) pl[t] = src[t];
    __syncthreads();
    float a = gg[o]*d_r1[o];
    float b2 = bb[o] - d_m1[o]*a;
    for (int t = tid; t < 33*64; t += 256) {
        int w = t & 63, i = t >> 6;
        float acc = 0.f;
        #pragma unroll 16
        for (int h = 0; h < 64; h++) acc += d_D64[i*64+h] * pl[h*64 + w];
        d_qkvR[((size_t)(n*256+o)*33 + i)*64 + w] = acc*a + b2;
    }
}

// sim (interleaved [part][w]) + BN2 partial stats
__global__ void __launch_bounds__(64) k_sim() {
    __shared__ float sh[6*64];
    int i = blockIdx.x, g = blockIdx.y, n = blockIdx.z, w = threadIdx.x;
    float qa[8];
    #pragma unroll
    for (int c = 0; c < 8; c++)
        qa[c] = d_qkvR[((size_t)(n*256 + g*32 + c)*33 + i)*64 + w];
    size_t rowbase = (((size_t)(n*8+g)*33 + i)*33)*192;
    float p[6] = {0.f,0.f,0.f,0.f,0.f,0.f};
    for (int j = 0; j < 33; j++) {
        float qk = 0.f, kr = 0.f, qr = 0.f;
        #pragma unroll
        for (int c = 0; c < 8; c++) {
            float kv = d_qkvR[((size_t)(n*256 + g*32 + 8 + c)*33 + j)*64 + w];
            qk += qa[c]*kv;
            kr += kv * d_pos[(8+c)*1089 + j*33 + i];
            qr += qa[c] * d_pos[c*1089 + i*33 + j];
        }
        d_sim[rowbase + j*192 + w]       = qk;
        d_sim[rowbase + j*192 + 64 + w]  = qr;
        d_sim[rowbase + j*192 + 128 + w] = kr;
        p[0] += qk; p[1] += qk*qk;
        p[2] += qr; p[3] += qr*qr;
        p[4] += kr; p[5] += kr*kr;
    }
    #pragma unroll
    for (int r = 0; r < 6; r++) sh[r*64 + w] = p[r];
    __syncthreads();
    for (int st = 32; st > 0; st >>= 1) {
        if (w < st) {
            #pragma unroll
            for (int r = 0; r < 6; r++) sh[r*64 + w] += sh[r*64 + w + st];
        }
        __syncthreads();
    }
    if (w == 0) {
        int base = (n*8+g)*33 + i;
        #pragma unroll
        for (int t = 0; t < 3; t++) {
            d_p2s[t*2112 + base] = sh[(2*t)*64];
            d_p2q[t*2112 + base] = sh[(2*t+1)*64];
        }
    }
}

__global__ void k_bn2() {
    __shared__ float ss[33], qq[33];
    int b = blockIdx.x;            // n*24 + ch
    int n = b / 24, ch = b % 24;
    int t = ch >> 3, g = ch & 7;
    int i = threadIdx.x;
    if (i < 33) {
        int idx = t*2112 + (n*8+g)*33 + i;
        ss[i] = d_p2s[idx];
        qq[i] = d_p2q[idx];
    }
    __syncthreads();
    if (i == 0) {
        float s = 0.f, q = 0.f;
        for (int k = 0; k < 33; k++) { s += ss[k]; q += qq[k]; }
        float m = s/69696.f;
        d_m2[b] = m;
        d_r2[b] = rsqrtf(q/69696.f - m*m + 1e-5f);
    }
}

// vb: [n][g][c][x][w]
__global__ void k_vb() {
    int idx = blockIdx.x * blockDim.x + threadIdx.x;
    if (idx >= 8*8*16*64*64) return;
    int w = idx & 63, x = (idx>>6) & 63, c = (idx>>12) & 15;
    int g = (idx>>16) & 7, n = idx>>19;
    int j0, j1; float w0, w1; up_tap(x, j0, j1, w0, w1);
    size_t b = (size_t)(n*256 + g*32 + 16 + c)*2112 + w;
    d_vb[idx] = w0*d_qkvR[b + j0*64] + w1*d_qkvR[b + j1*64];
}

// fused: BN2-apply + 3-sum + y-interp + x-interp + softmax + attention + BN3 partials
__global__ void __launch_bounds__(64) k_softsv(const float* __restrict__ gg,
                                               const float* __restrict__ bb) {
    __shared__ float srj[33*64];
    __shared__ float ps[16][2][4];
    int y = blockIdx.x, g = blockIdx.y, n = blockIdx.z, w = threadIdx.x;
    int warp = w >> 5, lane = w & 31;
    int i0, i1; float v0, v1; up_tap(y, i0, i1, v0, v1);

    float a0, a1t, a2t, C = 0.f;
    {
        int sc0 = n*24 + g,      ch0 = g;
        int sc1 = n*24 + 8 + g,  ch1 = 8 + g;
        int sc2 = n*24 + 16 + g, ch2 = 16 + g;
        a0  = gg[ch0]*d_r2[sc0]; C += bb[ch0] - d_m2[sc0]*a0;
        a1t = gg[ch1]*d_r2[sc1]; C += bb[ch1] - d_m2[sc1]*a1t;
        a2t = gg[ch2]*d_r2[sc2]; C += bb[ch2] - d_m2[sc2]*a2t;
    }

    const float* r0 = d_sim + (((size_t)(n*8+g)*33 + i0)*33)*192;
    const float* r1 = d_sim + (((size_t)(n*8+g)*33 + i1)*33)*192;
    #pragma unroll 3
    for (int j = 0; j < 33; j++) {
        int off = j*192 + w;
        float acc = C;
        acc += a0 *(v0*r0[off]       + v1*r1[off]);
        acc += a1t*(v0*r0[off + 64]  + v1*r1[off + 64]);
        acc += a2t*(v0*r0[off + 128] + v1*r1[off + 128]);
        srj[j*64 + w] = acc;
    }
    // each thread reads only its own w column — no cross-thread sharing, no sync
    float row[64];
    #pragma unroll
    for (int x = 0; x < 64; x++) {
        int j0, j1; float u0, u1; up_tap(x, j0, j1, u0, u1);
        row[x] = u0*srj[j0*64 + w] + u1*srj[j1*64 + w];
    }
    float mx = row[0];
    #pragma unroll
    for (int x = 1; x < 64; x++) mx = fmaxf(mx, row[x]);
    float s = 0.f;
    #pragma unroll
    for (int x = 0; x < 64; x++) { row[x] = __expf(row[x]-mx); s += row[x]; }
    float inv = 1.f/s;
    #pragma unroll
    for (int x = 0; x < 64; x++) row[x] *= inv;

    const float* vbg = d_vb + ((size_t)(n*8+g)*16)*4096 + w;
    #pragma unroll 2
    for (int c = 0; c < 16; c++) {
        const float* vbp = vbg + (size_t)c*4096;
        const float* vep = d_veH + (c*64 + y)*64;
        float asv = 0.f, asve = 0.f;
        #pragma unroll 8
        for (int x = 0; x < 64; x++) {
            float sx = row[x];
            asv  += sx * vbp[x*64];
            asve += sx * vep[x];
        }
        int ch = g*32 + c*2;
        size_t ob = ((size_t)(n*256 + ch)*64 + y)*64 + w;
        d_so[ob] = asv;
        d_so[ob + 4096] = asve;
        float t0 = asv, t1 = asv*asv, t2 = asve, t3 = asve*asve;
        #pragma unroll
        for (int st = 16; st > 0; st >>= 1) {
            t0 += __shfl_down_sync(0xffffffffu, t0, st);
            t1 += __shfl_down_sync(0xffffffffu, t1, st);
            t2 += __shfl_down_sync(0xffffffffu, t2, st);
            t3 += __shfl_down_sync(0xffffffffu, t3, st);
        }
        if (lane == 0) { ps[c][warp][0]=t0; ps[c][warp][1]=t1; ps[c][warp][2]=t2; ps[c][warp][3]=t3; }
    }
    __syncthreads();
    if (w < 16) {
        int blk = ((n*8+g)*64 + y);
        #pragma unroll
        for (int comp = 0; comp < 4; comp++)
            d_p3[((size_t)blk*16 + w)*4 + comp] = ps[w][0][comp] + ps[w][1][comp];
    }
}

// bn3 from partials
__global__ void k_bn3r() {
    __shared__ float sh1[128], sh2[128];
    int ch = blockIdx.x;
    int g = ch >> 5, c = (ch & 31) >> 1, e = ch & 1;
    int tid = threadIdx.x;
    float s = 0.f, q = 0.f;
    for (int t = tid; t < 512; t += 128) {
        int n = t >> 6, y = t & 63;
        size_t idx = ((size_t)((n*8+g)*64 + y)*16 + c)*4 + e*2;
        s += d_p3[idx]; q += d_p3[idx+1];
    }
    sh1[tid] = s; sh2[tid] = q;
    __syncthreads();
    for (int st = 64; st > 0; st >>= 1) {
        if (tid < st) { sh1[tid] += sh1[tid+st]; sh2[tid] += sh2[tid+st]; }
        __syncthreads();
    }
    if (tid == 0) {
        float m = sh1[0]*(1.f/32768.f);
        d_m3[ch] = m;
        d_r3[ch] = rsqrtf(sh2[0]*(1.f/32768.f) - m*m + 1e-5f);
    }
}

// o = BN3(so)[2oc]+BN3(so)[2oc+1], plus bn4 strip partials; one block per (n,oc)
__global__ void __launch_bounds__(256) k_o(const float* __restrict__ gg,
                                           const float* __restrict__ bb) {
    int oc = blockIdx.x & 127, n = blockIdx.x >> 7;
    int tid = threadIdx.x;
    float a0, b0, a1, b1;
    {
        int c0 = 2*oc, c1 = 2*oc + 1;
        a0 = gg[c0]*d_r3[c0]; b0 = bb[c0] - d_m3[c0]*a0;
        a1 = gg[c1]*d_r3[c1]; b1 = bb[c1] - d_m3[c1]*a1;
    }
    const float* p0 = d_so + (size_t)(n*256 + 2*oc)*4096;
    const float* p1 = p0 + 4096;
    float* po = d_o + (size_t)(n*128 + oc)*4096;
    float acc10[10];
    #pragma unroll
    for (int r = 0; r < 10; r++) acc10[r] = 0.f;
    for (int t = tid; t < 4096; t += 256) {
        float v = p0[t]*a0 + b0 + p1[t]*a1 + b1;
        po[t] = v;
        float v2 = v*v;
        acc10[0] += v; acc10[1] += v2;
        int w = t & 63, h = t >> 6;
        if (w < 2)  { acc10[2] += v; acc10[3] += v2; }
        if (w >= 62){ acc10[4] += v; acc10[5] += v2; }
        if (h < 2)  { acc10[6] += v; acc10[7] += v2; }
        if (h >= 62){ acc10[8] += v; acc10[9] += v2; }
    }
    #pragma unroll
    for (int r = 0; r < 10; r += 2) reduce2(acc10[r], acc10[r+1]);
    if (tid == 0) {
        #pragma unroll
        for (int r = 0; r < 10; r++) d_s4[(n*128 + oc)*10 + r] = acc10[r];
    }
}

// bn4 stats from strip partials
__global__ void k_bn4r() {
    int idx = blockIdx.x*256 + threadIdx.x;
    if (idx >= 1024) return;
    int n = idx >> 7, ch = idx & 127;
    int sc = ch, sub = -1;
    if      (ch < 10) { sc = ch;      sub = 4; }
    else if (ch < 20) { sc = ch - 10; sub = 2; }
    else if (ch < 30) { sc = ch - 20; sub = 8; }
    else if (ch < 40) { sc = ch - 30; sub = 6; }
    const float* s4 = d_s4 + (n*128 + sc)*10;
    float S = s4[0], Q = s4[1];
    if (sub >= 0) { S -= s4[sub]; Q -= s4[sub+1]; }
    float m = S*(1.f/4096.f);
    d_m4[idx] = m;
    d_r4[idx] = rsqrtf(Q*(1.f/4096.f) - m*m + 1e-5f);
}

extern "C" void kernel_launch(void* const* d_in, const int* in_sizes, int n_in,
                              void* d_out, int out_size) {
    const float* x        = (const float*)d_in[0];
    const float* qkv_w    = (const float*)d_in[1];
    const float* bn_qkv_g = (const float*)d_in[2];
    const float* bn_qkv_b = (const float*)d_in[3];
    const float* base_rel = (const float*)d_in[4];
    const float* bn_sim_g = (const float*)d_in[5];
    const float* bn_sim_b = (const float*)d_in[6];
    const float* bn_out_g = (const float*)d_in[7];
    const float* bn_out_b = (const float*)d_in[8];
    const float* in_g     = (const float*)d_in[9];
    const float* in_b     = (const float*)d_in[10];
    const float* mlp_w1   = (const float*)d_in[11];
    const float* mlp_w2   = (const float*)d_in[12];
    float* out = (float*)d_out;

    float *pqkv, *po, *ph1, *pp1s, *pp1q;
    cudaGetSymbolAddress((void**)&pqkv, d_qkv);
    cudaGetSymbolAddress((void**)&po,   d_o);
    cudaGetSymbolAddress((void**)&ph1,  d_h1);
    cudaGetSymbolAddress((void**)&pp1s, d_p1s);
    cudaGetSymbolAddress((void**)&pp1q, d_p1q);

    k_weights<<<1, 64>>>();
    k_pos1<<<(32*33*127 + 255)/256, 256>>>(base_rel);
    k_pos2<<<(32*33*33 + 255)/256, 256>>>();
    k_gemm_t<0><<<dim3(32, 4, 8), 256>>>(qkv_w, x, pqkv, nullptr, pp1s, pp1q, 256, 128);
    k_bn1r<<<256, 64>>>();
    k_resizeH<<<dim3(256, 8), 256>>>(bn_qkv_g, bn_qkv_b);
    k_sim<<<dim3(33, 8, 8), 64>>>();
    k_bn2<<<192, 64>>>();
    k_veh1<<<(16*64*33 + 255)/256, 256>>>();
    k_veh2<<<(16*64*64 + 255)/256, 256>>>();
    k_vb<<<(8*8*16*64*64 + 255)/256, 256>>>();
    k_softsv<<<dim3(64, 8, 8), 64>>>(bn_sim_g, bn_sim_b);
    k_bn3r<<<256, 128>>>();
    k_o<<<1024, 256>>>(bn_out_g, bn_out_b);
    k_bn4r<<<4, 256>>>();
    k_gemm_t<1><<<dim3(32, 8, 8), 256>>>(mlp_w1, po, ph1, nullptr,
                                         (float*)in_g, (float*)in_b, 512, 128);
    k_gemm_t<2><<<dim3(32, 2, 8), 256>>>(mlp_w2, ph1, out, po, nullptr, nullptr, 128, 512);
}